// round 9
// baseline (speedup 1.0000x reference)
#include <cuda_runtime.h>
#include <cuda_fp16.h>
#include <math.h>
#include <stdint.h>

// ---------------------------------------------------------------------------
// LatentMixer on GB300 (sm_103 plain target): single-term fp16 HMMA GEMMs,
// split kv/q GEMM with cross-stream overlap, fused attention.
// B=8, C=512, N=4096, heads=8, d=64, L=16, scale=0.125
// ---------------------------------------------------------------------------

#define Bsz 8
#define C   512
#define NPIX 4096
#define L   16
#define HEADS 8
#define DH  64
#define SCALE 0.125f
#define EPSN 1e-12f
#define KDIM 512
#define MROWS 1536   // stacked k(512) v(512) q(512)

// ---------------- scratch (device globals; allocation-free contract) -------
__device__ __half g_kvq[(size_t)Bsz * MROWS * NPIX];   // fp16 k/v/q
__device__ float g_lsum[64 * 4 * L];
__device__ float g_latpart[4 * 64 * DH * L];
__device__ float g_kvl[Bsz * 2 * C * L];
__device__ float g_qlhat[C * L];
__device__ __half g_xT [(size_t)Bsz * NPIX * C];       // x transposed fp16
__device__ __half g_xwT[(size_t)Bsz * NPIX * C];       // attn2 out fp16
__device__ __half g_wA[MROWS * KDIM];                  // stacked w_kv_x ; w_q_x
__device__ __half g_wp[C * KDIM];                      // w_proj

// ---------------- helpers ---------------------------------------------------
__device__ __forceinline__ uint32_t smem_u32(const void* p) {
    uint32_t a;
    asm("{ .reg .u64 t; cvta.to.shared.u64 t, %1; cvt.u32.u64 %0, t; }" : "=r"(a) : "l"(p));
    return a;
}

#define LDSM4(r, addr) \
    asm volatile("ldmatrix.sync.aligned.m8n8.x4.shared.b16 {%0,%1,%2,%3}, [%4];" \
                 : "=r"((r)[0]), "=r"((r)[1]), "=r"((r)[2]), "=r"((r)[3]) : "r"(addr))

#define MMA16816(cc, aa, b0, b1) \
    asm volatile("mma.sync.aligned.m16n8k16.row.col.f32.f16.f16.f32 " \
                 "{%0,%1,%2,%3}, {%4,%5,%6,%7}, {%8,%9}, {%0,%1,%2,%3};" \
                 : "+f"((cc)[0]), "+f"((cc)[1]), "+f"((cc)[2]), "+f"((cc)[3]) \
                 : "r"((aa)[0]), "r"((aa)[1]), "r"((aa)[2]), "r"((aa)[3]), \
                   "r"(b0), "r"(b1))

#define CP_ASYNC16(dst, src) \
    asm volatile("cp.async.cg.shared.global [%0], [%1], 16;" :: "r"(dst), "l"(src))
#define CP_COMMIT() asm volatile("cp.async.commit_group;" ::: "memory")
#define CP_WAIT(n)  asm volatile("cp.async.wait_group %0;" :: "n"(n) : "memory")

// ---------------------------------------------------------------------------
// Weight convert: fp32 -> fp16
// ---------------------------------------------------------------------------
__global__ __launch_bounds__(256) void wconv_kernel(
    const float* __restrict__ a, __half* __restrict__ hi, int n4)
{
    int i = blockIdx.x * 256 + threadIdx.x;
    if (i >= n4) return;
    float4 v = ((const float4*)a)[i];
    __half2* o = (__half2*)(hi + i * 4);
    o[0] = __floats2half2_rn(v.x, v.y);
    o[1] = __floats2half2_rn(v.z, v.w);
}

// ---------------------------------------------------------------------------
// Transpose x: [B,C,N] fp32 -> [B,N,C] fp16. 32x32 tiles.
// ---------------------------------------------------------------------------
__global__ __launch_bounds__(256) void tconv_kernel(
    const float* __restrict__ x, __half* __restrict__ xo)
{
    __shared__ float t[32][33];
    int n0 = blockIdx.x * 32, c0 = blockIdx.y * 32, b = blockIdx.z;
    int tx = threadIdx.x, ty = threadIdx.y;
    const float* xb = x + (size_t)b * C * NPIX;
    #pragma unroll
    for (int i = 0; i < 4; i++)
        t[ty + i * 8][tx] = xb[(size_t)(c0 + ty + i * 8) * NPIX + n0 + tx];
    __syncthreads();
    __half* ob = xo + (size_t)b * NPIX * C;
    #pragma unroll
    for (int i = 0; i < 4; i++)
        ob[(size_t)(n0 + ty + i * 8) * C + c0 + tx] = __float2half_rn(t[tx][ty + i * 8]);
}

// ---------------------------------------------------------------------------
// HMMA GEMM: C[z][m][n] = sum_k A[m][k]*B[z][n][k], single fp16 term.
// Tile 128x128x64, 256 threads (2x4 warps), 3-stage cp.async, 2 CTAs/SM.
// Output base Ch/Cf is pre-offset by the row base; Mstride = z-stride (elems).
// ---------------------------------------------------------------------------
#define STG 32768
__device__ __forceinline__ void gemm_load_stage(
    char* sm, int stg, int ck, int tid,
    const __half* a0, const __half* b0)
{
    char* d = sm + stg * STG;
    #pragma unroll
    for (int i = 0; i < 8; i++) {
        int u = tid + i * 256;
        int r = u >> 10, idx = u & 1023, row = idx >> 3, c = idx & 7;
        const __half* src = ((r == 0) ? a0 : b0) + (size_t)row * KDIM + ck * 64 + c * 8;
        uint32_t dst = smem_u32(d + r * 16384 + row * 128 + (((c ^ (row & 7))) << 4));
        CP_ASYNC16(dst, src);
    }
    CP_COMMIT();
}

__global__ __launch_bounds__(256, 2) void gemm_mma(
    const __half* __restrict__ A, const __half* __restrict__ B,
    __half* __restrict__ Ch, float* __restrict__ Cf,
    const float* __restrict__ bias, size_t Mstride)
{
    extern __shared__ char sm[];
    int tid = threadIdx.x, lane = tid & 31, wid = tid >> 5;
    int wm = wid >> 2, wn = wid & 3;
    int m0 = blockIdx.y * 128, n0 = blockIdx.x * 128, z = blockIdx.z;

    const __half* a0p = A + (size_t)m0 * KDIM;
    const __half* b0p = B + ((size_t)z * NPIX + n0) * KDIM;

    float acc[4][4][4];
    #pragma unroll
    for (int i = 0; i < 4; i++)
        #pragma unroll
        for (int j = 0; j < 4; j++)
            #pragma unroll
            for (int k = 0; k < 4; k++) acc[i][j][k] = 0.f;

    gemm_load_stage(sm, 0, 0, tid, a0p, b0p);
    gemm_load_stage(sm, 1, 1, tid, a0p, b0p);

    int a_row = wm * 64 + ((lane >> 3) & 1) * 8 + (lane & 7);
    int a_ck  = (lane >> 4);
    int b_row = wn * 32 + (lane >> 4) * 8 + (lane & 7);
    int b_ck  = ((lane >> 3) & 1);
    uint32_t sbase = smem_u32(sm);

    for (int ck = 0; ck < 8; ck++) {
        if (ck + 2 < 8) {
            gemm_load_stage(sm, (ck + 2) % 3, ck + 2, tid, a0p, b0p);
            CP_WAIT(2);
        } else if (ck + 1 < 8) {
            CP_WAIT(1);
        } else {
            CP_WAIT(0);
        }
        __syncthreads();

        uint32_t st = sbase + (ck % 3) * STG;
        #pragma unroll
        for (int kk = 0; kk < 4; kk++) {
            uint32_t af[4][4];
            #pragma unroll
            for (int mf = 0; mf < 4; mf++) {
                int row = a_row + mf * 16;
                int chv = (kk * 2 + a_ck) ^ (row & 7);
                LDSM4(af[mf], st + row * 128 + (chv << 4));
            }
            uint32_t bf[2][4];
            #pragma unroll
            for (int ng = 0; ng < 2; ng++) {
                int row = b_row + ng * 16;
                int chv = (kk * 2 + b_ck) ^ (row & 7);
                LDSM4(bf[ng], st + 16384 + row * 128 + (chv << 4));
            }
            #pragma unroll
            for (int mf = 0; mf < 4; mf++)
                #pragma unroll
                for (int ng = 0; ng < 2; ng++)
                    #pragma unroll
                    for (int nh = 0; nh < 2; nh++)
                        MMA16816(acc[mf][ng * 2 + nh], af[mf],
                                 bf[ng][nh * 2], bf[ng][nh * 2 + 1]);
        }
        __syncthreads();
    }

    size_t obase = (size_t)z * Mstride;
    if (Ch) {
        #pragma unroll
        for (int mf = 0; mf < 4; mf++) {
            int m = m0 + wm * 64 + mf * 16 + (lane >> 2);
            #pragma unroll
            for (int nf = 0; nf < 4; nf++) {
                int n = n0 + wn * 32 + nf * 8 + (lane & 3) * 2;
                *(__half2*)&Ch[obase + (size_t)m * NPIX + n] =
                    __floats2half2_rn(acc[mf][nf][0], acc[mf][nf][1]);
                *(__half2*)&Ch[obase + (size_t)(m + 8) * NPIX + n] =
                    __floats2half2_rn(acc[mf][nf][2], acc[mf][nf][3]);
            }
        }
    } else {
        #pragma unroll
        for (int mf = 0; mf < 4; mf++) {
            int m = m0 + wm * 64 + mf * 16 + (lane >> 2);
            float bb0 = bias ? bias[m] : 0.f;
            float bb8 = bias ? bias[m + 8] : 0.f;
            #pragma unroll
            for (int nf = 0; nf < 4; nf++) {
                int n = n0 + wn * 32 + nf * 8 + (lane & 3) * 2;
                *(float2*)&Cf[obase + (size_t)m * NPIX + n] =
                    make_float2(acc[mf][nf][0] + bb0, acc[mf][nf][1] + bb0);
                *(float2*)&Cf[obase + (size_t)(m + 8) * NPIX + n] =
                    make_float2(acc[mf][nf][2] + bb8, acc[mf][nf][3] + bb8);
            }
        }
    }
}

// ---------------------------------------------------------------------------
// qlhat: normalized latent queries (batch-invariant). grid=8, 256 threads.
// ---------------------------------------------------------------------------
__global__ __launch_bounds__(256) void qlhat_kernel(
    const float* __restrict__ w_q_lat, const float* __restrict__ latents,
    float* __restrict__ qlhat)
{
    int h = blockIdx.x;
    __shared__ float slat[C][L];
    __shared__ float stile[DH][L];
    __shared__ float snorm[L];
    int tid = threadIdx.x;
    for (int i = tid; i < C * L; i += 256) slat[i >> 4][i & 15] = latents[i];
    __syncthreads();
    for (int p = tid; p < DH * L; p += 256) {
        int j = p >> 4, l = p & 15;
        const float* wrow = w_q_lat + (size_t)(h * DH + j) * C;
        float acc = 0.f;
        for (int c2 = 0; c2 < C; c2++) acc += wrow[c2] * slat[c2][l];
        stile[j][l] = acc;
    }
    __syncthreads();
    if (tid < L) {
        float s = 0.f;
        for (int j = 0; j < DH; j++) { float v = stile[j][tid]; s += v * v; }
        snorm[tid] = 1.f / fmaxf(sqrtf(s), EPSN);
    }
    __syncthreads();
    for (int p = tid; p < DH * L; p += 256)
        qlhat[(h * DH + (p >> 4)) * L + (p & 15)] = stile[p >> 4][p & 15] * snorm[p & 15];
}

// ---------------------------------------------------------------------------
// attn1 fused: per (bh, split of 1024 px): exp(logits) -> smem tile [16][1024],
// per-split L-sums -> lsum_g, unnormalized partial P@V -> latpart.
// grid (64, 4), 512 threads, ~69KB dynamic smem.
// ---------------------------------------------------------------------------
__global__ __launch_bounds__(512) void attn1_fused_kernel(
    const __half* __restrict__ kvq, const float* __restrict__ qlhat,
    float* __restrict__ latpart, float* __restrict__ lsum_g)
{
    extern __shared__ float dyn[];
    float* p_sm = dyn;                       // [16][1024] = 64KB
    float (*sql)[L] = (float(*)[L])(dyn + L * 1024);   // [64][16]
    float (*wred)[L] = (float(*)[L])(dyn + L * 1024 + DH * L); // [16][16]

    int bh = blockIdx.x, split = blockIdx.y, b = bh >> 3, h = bh & 7;
    const __half* kbase = kvq + ((size_t)b * MROWS + h * DH) * NPIX + split * 1024;
    const __half* vbase = kvq + ((size_t)b * MROWS + 512 + h * DH) * NPIX + split * 1024;
    int tid = threadIdx.x, lane = tid & 31, wrp = tid >> 5;

    for (int i = tid; i < DH * L; i += 512)
        sql[i >> 4][i & 15] = qlhat[(h * DH + (i >> 4)) * L + (i & 15)];
    __syncthreads();

    // phase 1: 2 pixels per thread
    {
        float dot[2][L], nrm[2] = {0.f, 0.f};
        #pragma unroll
        for (int i = 0; i < 2; i++)
            #pragma unroll
            for (int l = 0; l < L; l++) dot[i][l] = 0.f;
        for (int j = 0; j < DH; j++) {
            __half2 a01 = *(const __half2*)(kbase + (size_t)j * NPIX + 2 * tid);
            float k0 = __low2float(a01), k1 = __high2float(a01);
            nrm[0] += k0 * k0; nrm[1] += k1 * k1;
            #pragma unroll
            for (int l = 0; l < L; l++) {
                float s = sql[j][l];
                dot[0][l] += k0 * s;
                dot[1][l] += k1 * s;
            }
        }
        float inv0 = SCALE / fmaxf(sqrtf(nrm[0]), EPSN);
        float inv1 = SCALE / fmaxf(sqrtf(nrm[1]), EPSN);
        float lsum[L];
        #pragma unroll
        for (int l = 0; l < L; l++) {
            float p0 = __expf(dot[0][l] * inv0);
            float p1 = __expf(dot[1][l] * inv1);
            lsum[l] = p0 + p1;
            *(float2*)&p_sm[l * 1024 + 2 * tid] = make_float2(p0, p1);
        }
        #pragma unroll
        for (int l = 0; l < L; l++) {
            float v = lsum[l];
            #pragma unroll
            for (int o = 16; o; o >>= 1) v += __shfl_xor_sync(0xffffffffu, v, o);
            if (lane == 0) wred[wrp][l] = v;
        }
    }
    __syncthreads();
    if (tid < L) {
        float s = 0.f;
        #pragma unroll
        for (int w = 0; w < 16; w++) s += wred[w][tid];
        lsum_g[bh * 64 + split * 16 + tid] = s;
    }

    // phase 2: warp wrp owns rows j in [4*wrp, 4*wrp+4); unnormalized P@V
    float acc[4][L];
    #pragma unroll
    for (int jj = 0; jj < 4; jj++)
        #pragma unroll
        for (int l = 0; l < L; l++) acc[jj][l] = 0.f;

    for (int it = 0; it < 16; it++) {
        int n2 = it * 64 + lane * 2;
        float2 pv[L];
        #pragma unroll
        for (int l = 0; l < L; l++) pv[l] = *(const float2*)&p_sm[l * 1024 + n2];
        #pragma unroll
        for (int jj = 0; jj < 4; jj++) {
            __half2 v2 = *(const __half2*)&vbase[(size_t)(wrp * 4 + jj) * NPIX + n2];
            float v0 = __low2float(v2), v1 = __high2float(v2);
            #pragma unroll
            for (int l = 0; l < L; l++) acc[jj][l] += v0 * pv[l].x + v1 * pv[l].y;
        }
    }
    #pragma unroll
    for (int jj = 0; jj < 4; jj++)
        #pragma unroll
        for (int l = 0; l < L; l++) {
            float v = acc[jj][l];
            #pragma unroll
            for (int o = 16; o; o >>= 1) v += __shfl_xor_sync(0xffffffffu, v, o);
            if (lane == 0)
                latpart[split * 65536 + bh * 1024 + (wrp * 4 + jj) * 16 + l] = v;
        }
}

// ---------------------------------------------------------------------------
// kvl (fused with attn1d): reconstruct latread[b] from latpart/lsum inline,
// then kvl[b] = w_kv_lat @ latread[b]; normalize k-part. grid (8,16).
// ---------------------------------------------------------------------------
__global__ __launch_bounds__(256) void kvl_kernel(
    const float* __restrict__ w_kv_lat, const float* __restrict__ latpart,
    const float* __restrict__ lsum_g, float* __restrict__ kvl)
{
    int b = blockIdx.x, c0 = blockIdx.y * 64;
    __shared__ float slat[C][L];
    __shared__ float stile[64][L];
    __shared__ float snorm[L];
    int tid = threadIdx.x;
    // reconstruct latread[b][c][l] = (sum_sp latpart) / (sum_sp lsum)
    for (int i = tid; i < C * L; i += 256) {
        int c = i >> 4, l = i & 15;
        int h = c >> 6, r = c & 63;
        int bh = b * 8 + h;
        int e = bh * 1024 + r * 16 + l;
        float s = latpart[e] + latpart[65536 + e] + latpart[131072 + e] + latpart[196608 + e];
        float d = lsum_g[bh * 64 + l] + lsum_g[bh * 64 + 16 + l] +
                  lsum_g[bh * 64 + 32 + l] + lsum_g[bh * 64 + 48 + l];
        slat[c][l] = s / d;
    }
    __syncthreads();
    for (int p = tid; p < 64 * L; p += 256) {
        int j = p >> 4, l = p & 15;
        const float* wrow = w_kv_lat + (size_t)(c0 + j) * C;
        float acc = 0.f;
        for (int c2 = 0; c2 < C; c2++) acc += wrow[c2] * slat[c2][l];
        stile[j][l] = acc;
    }
    __syncthreads();
    if (c0 < C) {
        if (tid < L) {
            float s = 0.f;
            for (int j = 0; j < 64; j++) { float v = stile[j][tid]; s += v * v; }
            snorm[tid] = 1.f / fmaxf(sqrtf(s), EPSN);
        }
        __syncthreads();
        for (int p = tid; p < 64 * L; p += 256)
            kvl[((size_t)b * 2 * C + c0 + (p >> 4)) * L + (p & 15)] =
                stile[p >> 4][p & 15] * snorm[p & 15];
    } else {
        for (int p = tid; p < 64 * L; p += 256)
            kvl[((size_t)b * 2 * C + c0 + (p >> 4)) * L + (p & 15)] = stile[p >> 4][p & 15];
    }
}

// ---------------------------------------------------------------------------
// attn2: latent write; 2 pixels/thread via half2 q loads; fp16 xwT out.
// grid (16, HEADS, Bsz), 128 threads (256 px/block).
// ---------------------------------------------------------------------------
__global__ __launch_bounds__(128) void attn2_kernel(
    const __half* __restrict__ kvq, const float* __restrict__ kvl,
    __half* __restrict__ xwT)
{
    int b = blockIdx.z, h = blockIdx.y;
    int tid = threadIdx.x;
    int n = blockIdx.x * 256 + 2 * tid;
    __shared__ float skl[DH][L];
    __shared__ float svl[DH][L];
    __shared__ unsigned short sh[DH][256];

    const float* kvlb = kvl + (size_t)b * 2 * C * L;
    for (int i = tid; i < DH * L; i += 128) {
        skl[i >> 4][i & 15] = kvlb[(h * DH + (i >> 4)) * L + (i & 15)];
        svl[i >> 4][i & 15] = kvlb[(C + h * DH + (i >> 4)) * L + (i & 15)];
    }
    __syncthreads();

    const __half* qcol = kvq + ((size_t)b * MROWS + 1024 + h * DH) * NPIX + n;
    float dot[2][L], nrm[2] = {0.f, 0.f};
    #pragma unroll
    for (int i = 0; i < 2; i++)
        #pragma unroll
        for (int l = 0; l < L; l++) dot[i][l] = 0.f;
    for (int j = 0; j < DH; j++) {
        __half2 q2 = *(const __half2*)(qcol + (size_t)j * NPIX);
        float q0 = __low2float(q2), q1 = __high2float(q2);
        nrm[0] += q0 * q0; nrm[1] += q1 * q1;
        #pragma unroll
        for (int l = 0; l < L; l++) {
            float s = skl[j][l];
            dot[0][l] += q0 * s;
            dot[1][l] += q1 * s;
        }
    }
    float is[2];
    #pragma unroll
    for (int i = 0; i < 2; i++) {
        float inv = SCALE / fmaxf(sqrtf(nrm[i]), EPSN);
        float s = 0.f;
        #pragma unroll
        for (int l = 0; l < L; l++) { dot[i][l] = __expf(dot[i][l] * inv); s += dot[i][l]; }
        is[i] = 1.f / s;
    }

    for (int j = 0; j < DH; j++) {
        float a0 = 0.f, a1 = 0.f;
        #pragma unroll
        for (int l = 0; l < L; l++) {
            float v = svl[j][l];
            a0 += dot[0][l] * v;
            a1 += dot[1][l] * v;
        }
        sh[j][2 * tid]     = __half_as_ushort(__float2half_rn(a0 * is[0]));
        sh[j][2 * tid + 1] = __half_as_ushort(__float2half_rn(a1 * is[1]));
    }
    __syncthreads();

    #pragma unroll
    for (int px = 0; px < 2; px++) {
        int pp = 2 * tid + px;
        int np = blockIdx.x * 256 + pp;
        size_t base = ((size_t)b * NPIX + np) * C + h * DH;
        #pragma unroll
        for (int c4 = 0; c4 < 8; c4++) {
            uint32_t wv[4];
            #pragma unroll
            for (int k = 0; k < 4; k++) {
                int j = c4 * 8 + k * 2;
                wv[k] = (uint32_t)sh[j][pp] | ((uint32_t)sh[j + 1][pp] << 16);
            }
            *(uint4*)(xwT + base + c4 * 8) = make_uint4(wv[0], wv[1], wv[2], wv[3]);
        }
    }
}

// ---------------------------------------------------------------------------
// Launch: fork/join stream DAG.
//   s1: weight conversions for kv+q (evA)
//   s2: w_proj conversion + qlhat (evSide)
//   s3: gemm_q after (tconv & evA) -> evQ, overlaps attn1+kvl
// ---------------------------------------------------------------------------
extern "C" void kernel_launch(void* const* d_in, const int* in_sizes, int n_in,
                              void* d_out, int out_size)
{
    const float* x        = (const float*)d_in[0];
    const float* latents  = (const float*)d_in[1];
    const float* w_q_lat  = (const float*)d_in[2];
    const float* w_kv_x   = (const float*)d_in[3];
    const float* w_q_x    = (const float*)d_in[4];
    const float* w_kv_lat = (const float*)d_in[5];
    const float* w_proj   = (const float*)d_in[6];
    const float* b_proj   = (const float*)d_in[7];
    float* out = (float*)d_out;

    float *lsum, *latpart, *kvl, *qlhat;
    __half *kvq, *xT, *xwT, *wA, *wp;
    cudaGetSymbolAddress((void**)&kvq, g_kvq);
    cudaGetSymbolAddress((void**)&lsum, g_lsum);
    cudaGetSymbolAddress((void**)&latpart, g_latpart);
    cudaGetSymbolAddress((void**)&kvl, g_kvl);
    cudaGetSymbolAddress((void**)&qlhat, g_qlhat);
    cudaGetSymbolAddress((void**)&xT, g_xT);
    cudaGetSymbolAddress((void**)&xwT, g_xwT);
    cudaGetSymbolAddress((void**)&wA, g_wA);
    cudaGetSymbolAddress((void**)&wp, g_wp);

    static cudaStream_t s1 = nullptr, s2 = nullptr, s3 = nullptr;
    static cudaEvent_t evFork = nullptr, evA = nullptr, evSide = nullptr,
                       evT = nullptr, evQ = nullptr;
    if (!s1) {
        cudaStreamCreateWithFlags(&s1, cudaStreamNonBlocking);
        cudaStreamCreateWithFlags(&s2, cudaStreamNonBlocking);
        cudaStreamCreateWithFlags(&s3, cudaStreamNonBlocking);
        cudaEventCreateWithFlags(&evFork, cudaEventDisableTiming);
        cudaEventCreateWithFlags(&evA, cudaEventDisableTiming);
        cudaEventCreateWithFlags(&evSide, cudaEventDisableTiming);
        cudaEventCreateWithFlags(&evT, cudaEventDisableTiming);
        cudaEventCreateWithFlags(&evQ, cudaEventDisableTiming);
    }

    cudaFuncSetAttribute(gemm_mma, cudaFuncAttributeMaxDynamicSharedMemorySize, 3 * STG);
    int attn1_smem = (L * 1024 + DH * L + 16 * L) * sizeof(float);
    cudaFuncSetAttribute(attn1_fused_kernel, cudaFuncAttributeMaxDynamicSharedMemorySize, attn1_smem);

    cudaEventRecord(evFork, 0);
    // s1: kv + q weight conversion
    cudaStreamWaitEvent(s1, evFork, 0);
    wconv_kernel<<<(2 * C * KDIM / 4 + 255) / 256, 256, 0, s1>>>(w_kv_x, wA, 2 * C * KDIM / 4);
    wconv_kernel<<<(C * KDIM / 4 + 255) / 256, 256, 0, s1>>>(w_q_x, wA + 2 * C * KDIM, C * KDIM / 4);
    cudaEventRecord(evA, s1);
    // s2: proj weight conversion + qlhat
    cudaStreamWaitEvent(s2, evFork, 0);
    wconv_kernel<<<(C * KDIM / 4 + 255) / 256, 256, 0, s2>>>(w_proj, wp, C * KDIM / 4);
    qlhat_kernel<<<HEADS, 256, 0, s2>>>(w_q_lat, latents, qlhat);
    cudaEventRecord(evSide, s2);

    // main: transpose x, then kv GEMM (rows 0..1024)
    tconv_kernel<<<dim3(NPIX / 32, C / 32, Bsz), dim3(32, 8)>>>(x, xT);
    cudaStreamWaitEvent(0, evA, 0);
    cudaEventRecord(evT, 0);
    gemm_mma<<<dim3(32, 8, Bsz), 256, 3 * STG>>>(wA, xT, kvq, nullptr, nullptr,
                                                 (size_t)MROWS * NPIX);
    // s3: q GEMM (rows 1024..1536), overlaps attn1+kvl below
    cudaStreamWaitEvent(s3, evT, 0);
    gemm_mma<<<dim3(32, 4, Bsz), 256, 3 * STG, s3>>>(wA + 2 * C * KDIM, xT,
                                                     kvq + (size_t)1024 * NPIX,
                                                     nullptr, nullptr,
                                                     (size_t)MROWS * NPIX);
    cudaEventRecord(evQ, s3);

    // main: latent read attention + kvl (needs qlhat)
    cudaStreamWaitEvent(0, evSide, 0);
    attn1_fused_kernel<<<dim3(64, 4), 512, attn1_smem>>>(kvq, qlhat, latpart, lsum);
    kvl_kernel<<<dim3(Bsz, 16), 256>>>(w_kv_lat, latpart, lsum, kvl);

    // main: latent write attention (needs q rows)
    cudaStreamWaitEvent(0, evQ, 0);
    attn2_kernel<<<dim3(16, HEADS, Bsz), 128>>>(kvq, kvl, xwT);

    // output projection + bias (fp32 out)
    gemm_mma<<<dim3(32, 4, Bsz), 256, 3 * STG>>>(wp, xwT, nullptr, out, b_proj,
                                                 (size_t)C * NPIX);
}